// round 2
// baseline (speedup 1.0000x reference)
#include <cuda_runtime.h>
#include <math.h>

#define NSLICE 16
#define LSEQ   2048
#define DLLM   768
#define EDIM   64
#define EPS    1e-5f

#define QTILE  128          // query rows per CTA
#define KTILE  128          // keys per inner tile
#define NQT    (LSEQ/QTILE) // 16
#define PP     132          // P smem row pitch (pad for bank spread)

__device__ float g_q[NSLICE * LSEQ * EDIM];
__device__ float g_k[NSLICE * LSEQ * EDIM];
__device__ float g_v[NSLICE * LSEQ * EDIM];
__device__ float g_o[NSLICE * LSEQ * EDIM];
__device__ float2 g_part[NSLICE * NQT];
__device__ float2 g_stats[NSLICE];

// ----------------------------------------------------------------------------
// Fused projection: q,k,v = info @ {Wq,Wk,Wv} + {bq,bk,bv}
// Tile 128 rows x (3 x 64) cols, BK=32, 256 threads, frag 8 x (3x4).
// ----------------------------------------------------------------------------
__global__ __launch_bounds__(256, 1)
void proj_fused_kernel(const float* __restrict__ X,
                       const float* __restrict__ Wq, const float* __restrict__ bq,
                       const float* __restrict__ Wk, const float* __restrict__ bk,
                       const float* __restrict__ Wv, const float* __restrict__ bv)
{
    __shared__ float As[128 * 33];      // [row][k] pitch 33 -> conflict-free
    __shared__ float Bs[3 * 32 * 64];   // [w][k][col]

    const int s    = blockIdx.y;
    const int row0 = blockIdx.x * 128;
    const int tx = threadIdx.x & 15;
    const int ty = threadIdx.x >> 4;
    const int tid = threadIdx.x;

    const float* Xs = X + (size_t)s * LSEQ * DLLM + (size_t)row0 * DLLM;
    const float* Wp[3] = {Wq, Wk, Wv};

    float acc[3][8][4];
    #pragma unroll
    for (int w = 0; w < 3; ++w)
        #pragma unroll
        for (int i = 0; i < 8; ++i)
            #pragma unroll
            for (int j = 0; j < 4; ++j) acc[w][i][j] = 0.f;

    for (int k0 = 0; k0 < DLLM; k0 += 32) {
        // A tile: 128 rows x 32 k. 1024 float4 loads, scatter to pitch-33 rows.
        #pragma unroll
        for (int t = 0; t < 4; ++t) {
            int f = tid + t * 256;            // 0..1023
            int r  = f >> 3;
            int kc = (f & 7) * 4;
            float4 v4 = *reinterpret_cast<const float4*>(&Xs[(size_t)r * DLLM + k0 + kc]);
            float* dst = &As[r * 33 + kc];
            dst[0] = v4.x; dst[1] = v4.y; dst[2] = v4.z; dst[3] = v4.w;
        }
        // B tiles: 3 x 32 x 64
        #pragma unroll
        for (int t = 0; t < 6; ++t) {
            int f = tid + t * 256;            // 0..1535 float4s
            int w   = f >> 9;                 // 512 float4 per weight
            int rem = f & 511;
            int kk  = rem >> 4;
            int c   = (rem & 15) * 4;
            *reinterpret_cast<float4*>(&Bs[w * 2048 + kk * 64 + c]) =
                *reinterpret_cast<const float4*>(&Wp[w][(size_t)(k0 + kk) * EDIM + c]);
        }
        __syncthreads();

        #pragma unroll 4
        for (int kk = 0; kk < 32; ++kk) {
            float a[8];
            #pragma unroll
            for (int i = 0; i < 8; ++i) a[i] = As[(ty * 8 + i) * 33 + kk];
            #pragma unroll
            for (int w = 0; w < 3; ++w) {
                float4 b4 = *reinterpret_cast<const float4*>(&Bs[w * 2048 + kk * 64 + tx * 4]);
                #pragma unroll
                for (int i = 0; i < 8; ++i) {
                    acc[w][i][0] += a[i] * b4.x;
                    acc[w][i][1] += a[i] * b4.y;
                    acc[w][i][2] += a[i] * b4.z;
                    acc[w][i][3] += a[i] * b4.w;
                }
            }
        }
        __syncthreads();
    }

    const float* bp[3] = {bq, bk, bv};
    float* Yp[3] = {g_q, g_k, g_v};
    #pragma unroll
    for (int w = 0; w < 3; ++w) {
        float4 bb = *reinterpret_cast<const float4*>(&bp[w][tx * 4]);
        float* Ys = Yp[w] + (size_t)s * LSEQ * EDIM + (size_t)row0 * EDIM;
        #pragma unroll
        for (int i = 0; i < 8; ++i) {
            float4 r4;
            r4.x = acc[w][i][0] + bb.x;
            r4.y = acc[w][i][1] + bb.y;
            r4.z = acc[w][i][2] + bb.z;
            r4.w = acc[w][i][3] + bb.w;
            *reinterpret_cast<float4*>(&Ys[(size_t)(ty * 8 + i) * EDIM + tx * 4]) = r4;
        }
    }
}

// ----------------------------------------------------------------------------
// Flash attention: 128 query rows/CTA, 128-key tiles, 256 threads.
// QK phase: (ty,tx) in 16x16 owns an 8x8 S fragment (1.0 B/FMA).
// PV phase: (ry,re) = (tid/8, tid%8) owns 4 rows x 8 E cols (1.5 B/FMA).
// Softmax state per row lives in SMEM (row_m/row_l/row_alpha).
// ----------------------------------------------------------------------------
__global__ __launch_bounds__(256, 1)
void attn_kernel()
{
    extern __shared__ float sm[];
    float* Qs = sm;                       // 128*64
    float* Ks = Qs + 128 * 64;            // 128*64, e-swizzled
    float* Vs = Ks + 128 * 64;            // 128*64
    float* Ps = Vs + 128 * 64;            // 128*PP
    float* row_m     = Ps + 128 * PP;     // 128
    float* row_l     = row_m + 128;       // 128
    float* row_alpha = row_l + 128;       // 128

    const int s    = blockIdx.y;
    const int row0 = blockIdx.x * QTILE;
    const int tid = threadIdx.x;
    const int tx = tid & 15, ty = tid >> 4;     // QK mapping
    const int re = tid & 7,  ry = tid >> 3;     // PV mapping

    const float* Qg = g_q + (size_t)s * LSEQ * EDIM + (size_t)row0 * EDIM;
    const float* Kg = g_k + (size_t)s * LSEQ * EDIM;
    const float* Vg = g_v + (size_t)s * LSEQ * EDIM;

    // Load Q tile (row-major), init softmax state
    #pragma unroll
    for (int t = 0; t < 8; ++t) {
        int f = tid + t * 256;            // 2048 float4s
        int r = f >> 4, c = (f & 15) * 4;
        *reinterpret_cast<float4*>(&Qs[r * 64 + c]) =
            *reinterpret_cast<const float4*>(&Qg[(size_t)r * EDIM + c]);
    }
    if (tid < 128) { row_m[tid] = -1e30f; row_l[tid] = 0.f; }

    float O[4][8];
    #pragma unroll
    for (int i = 0; i < 4; ++i)
        #pragma unroll
        for (int j = 0; j < 8; ++j) O[i][j] = 0.f;

    const float scale = 0.125f;
    const int kswz = (tx & 7) << 2;       // read-side K swizzle for this thread

    for (int kt = 0; kt < LSEQ / KTILE; ++kt) {
        __syncthreads();  // previous PV reads of Vs/Ps done

        // Load K (e-swizzled) and V tiles
        #pragma unroll
        for (int t = 0; t < 8; ++t) {
            int f = tid + t * 256;
            int r = f >> 4, c = (f & 15) * 4;
            float4 kv4 = *reinterpret_cast<const float4*>(&Kg[(size_t)(kt * KTILE + r) * EDIM + c]);
            int cs = c ^ (((r >> 3) & 7) << 2);
            *reinterpret_cast<float4*>(&Ks[r * 64 + cs]) = kv4;
            *reinterpret_cast<float4*>(&Vs[r * 64 + c]) =
                *reinterpret_cast<const float4*>(&Vg[(size_t)(kt * KTILE + r) * EDIM + c]);
        }
        __syncthreads();

        // ---- S = Q @ K^T, 8x8 fragment ----
        float S[8][8];
        #pragma unroll
        for (int i = 0; i < 8; ++i)
            #pragma unroll
            for (int j = 0; j < 8; ++j) S[i][j] = 0.f;

        #pragma unroll 2
        for (int e0 = 0; e0 < 64; e0 += 4) {
            float4 q4[8], k4[8];
            #pragma unroll
            for (int i = 0; i < 8; ++i)
                q4[i] = *reinterpret_cast<const float4*>(&Qs[(ty * 8 + i) * 64 + e0]);
            #pragma unroll
            for (int j = 0; j < 8; ++j)
                k4[j] = *reinterpret_cast<const float4*>(&Ks[(tx * 8 + j) * 64 + (e0 ^ kswz)]);
            #pragma unroll
            for (int i = 0; i < 8; ++i)
                #pragma unroll
                for (int j = 0; j < 8; ++j) {
                    S[i][j] += q4[i].x * k4[j].x;
                    S[i][j] += q4[i].y * k4[j].y;
                    S[i][j] += q4[i].z * k4[j].z;
                    S[i][j] += q4[i].w * k4[j].w;
                }
        }

        // ---- online softmax per row (16 tx lanes own a row) ----
        #pragma unroll
        for (int i = 0; i < 8; ++i) {
            int r = ty * 8 + i;
            float rmax = S[i][0];
            #pragma unroll
            for (int j = 1; j < 8; ++j) rmax = fmaxf(rmax, S[i][j]);
            #pragma unroll
            for (int off = 8; off; off >>= 1)
                rmax = fmaxf(rmax, __shfl_xor_sync(0xffffffffu, rmax, off));

            float old_m = row_m[r];
            float mn = fmaxf(old_m, scale * rmax);
            float rsum = 0.f;
            #pragma unroll
            for (int j = 0; j < 8; ++j) {
                float p = __expf(fmaf(scale, S[i][j], -mn));
                S[i][j] = p;
                rsum += p;
            }
            #pragma unroll
            for (int off = 8; off; off >>= 1)
                rsum += __shfl_xor_sync(0xffffffffu, rsum, off);

            if (tx == 0) {
                float alpha = __expf(old_m - mn);
                row_m[r] = mn;
                row_alpha[r] = alpha;
                row_l[r] = row_l[r] * alpha + rsum;
            }
            // store P row fragment (2 x float4)
            float4 p0 = make_float4(S[i][0], S[i][1], S[i][2], S[i][3]);
            float4 p1 = make_float4(S[i][4], S[i][5], S[i][6], S[i][7]);
            *reinterpret_cast<float4*>(&Ps[r * PP + tx * 8])     = p0;
            *reinterpret_cast<float4*>(&Ps[r * PP + tx * 8 + 4]) = p1;
        }
        __syncthreads();

        // ---- O = O*alpha + P @ V (PV mapping: 4 rows x 8 cols) ----
        #pragma unroll
        for (int i = 0; i < 4; ++i) {
            float a = row_alpha[ry * 4 + i];
            #pragma unroll
            for (int j = 0; j < 8; ++j) O[i][j] *= a;
        }

        #pragma unroll 2
        for (int mi = 0; mi < KTILE; mi += 4) {
            float4 p4[4];
            #pragma unroll
            for (int i = 0; i < 4; ++i)
                p4[i] = *reinterpret_cast<const float4*>(&Ps[(ry * 4 + i) * PP + mi]);
            float4 v4[4][2];
            #pragma unroll
            for (int mm = 0; mm < 4; ++mm) {
                v4[mm][0] = *reinterpret_cast<const float4*>(&Vs[(mi + mm) * 64 + re * 8]);
                v4[mm][1] = *reinterpret_cast<const float4*>(&Vs[(mi + mm) * 64 + re * 8 + 4]);
            }
            #pragma unroll
            for (int i = 0; i < 4; ++i) {
                const float pm[4] = {p4[i].x, p4[i].y, p4[i].z, p4[i].w};
                #pragma unroll
                for (int mm = 0; mm < 4; ++mm) {
                    O[i][0] += pm[mm] * v4[mm][0].x;
                    O[i][1] += pm[mm] * v4[mm][0].y;
                    O[i][2] += pm[mm] * v4[mm][0].z;
                    O[i][3] += pm[mm] * v4[mm][0].w;
                    O[i][4] += pm[mm] * v4[mm][1].x;
                    O[i][5] += pm[mm] * v4[mm][1].y;
                    O[i][6] += pm[mm] * v4[mm][1].z;
                    O[i][7] += pm[mm] * v4[mm][1].w;
                }
            }
        }
    }

    // ---- finalize, write g_o, instance-norm partials ----
    float lsum = 0.f, lsq = 0.f;
    float* Og = g_o + (size_t)s * LSEQ * EDIM + (size_t)row0 * EDIM;
    #pragma unroll
    for (int i = 0; i < 4; ++i) {
        float inv = 1.f / row_l[ry * 4 + i];
        float4 r0, r1;
        float o0 = O[i][0] * inv, o1 = O[i][1] * inv, o2 = O[i][2] * inv, o3 = O[i][3] * inv;
        float o4 = O[i][4] * inv, o5 = O[i][5] * inv, o6 = O[i][6] * inv, o7 = O[i][7] * inv;
        r0 = make_float4(o0, o1, o2, o3);
        r1 = make_float4(o4, o5, o6, o7);
        *reinterpret_cast<float4*>(&Og[(size_t)(ry * 4 + i) * EDIM + re * 8])     = r0;
        *reinterpret_cast<float4*>(&Og[(size_t)(ry * 4 + i) * EDIM + re * 8 + 4]) = r1;
        lsum += o0 + o1 + o2 + o3 + o4 + o5 + o6 + o7;
        lsq  += o0*o0 + o1*o1 + o2*o2 + o3*o3 + o4*o4 + o5*o5 + o6*o6 + o7*o7;
    }

    __syncthreads();                 // all Ps reads done; reuse as reduction scratch
    float* red  = Ps;
    float* red2 = Ps + 256;
    red[tid]  = lsum;
    red2[tid] = lsq;
    __syncthreads();
    #pragma unroll
    for (int st = 128; st; st >>= 1) {
        if (tid < st) { red[tid] += red[tid + st]; red2[tid] += red2[tid + st]; }
        __syncthreads();
    }
    if (tid == 0) g_part[s * NQT + blockIdx.x] = make_float2(red[0], red2[0]);
}

// ----------------------------------------------------------------------------
__global__ void stats_kernel()
{
    const int s = blockIdx.x;
    const int t = threadIdx.x;
    float sum = 0.f, sq = 0.f;
    if (t < NQT) {
        float2 p = g_part[s * NQT + t];
        sum = p.x; sq = p.y;
    }
    #pragma unroll
    for (int off = 16; off; off >>= 1) {
        sum += __shfl_xor_sync(0xffffffffu, sum, off);
        sq  += __shfl_xor_sync(0xffffffffu, sq,  off);
    }
    if (t == 0) {
        const float n = (float)(LSEQ * EDIM);
        float mu  = sum / n;
        float var = sq / n - mu * mu;
        g_stats[s] = make_float2(mu, rsqrtf(var + EPS));
    }
}

__global__ void norm_kernel(float* __restrict__ out)
{
    int idx4 = blockIdx.x * 256 + threadIdx.x;
    int base = idx4 * 4;
    int s = base / (LSEQ * EDIM);
    float2 st = g_stats[s];
    const float4 o = *reinterpret_cast<const float4*>(&g_o[base]);
    float4 r;
    r.x = (o.x - st.x) * st.y;
    r.y = (o.y - st.x) * st.y;
    r.z = (o.z - st.x) * st.y;
    r.w = (o.w - st.x) * st.y;
    *reinterpret_cast<float4*>(&out[base]) = r;
}

// ----------------------------------------------------------------------------
extern "C" void kernel_launch(void* const* d_in, const int* in_sizes, int n_in,
                              void* d_out, int out_size)
{
    const float* info = (const float*)d_in[0];
    const float* Wq   = (const float*)d_in[1];
    const float* bq   = (const float*)d_in[2];
    const float* Wk   = (const float*)d_in[3];
    const float* bk   = (const float*)d_in[4];
    const float* Wv   = (const float*)d_in[5];
    const float* bv   = (const float*)d_in[6];
    float* out = (float*)d_out;

    const int attn_smem = (128 * 64 * 3 + 128 * PP + 3 * 128) * (int)sizeof(float); // 167424
    cudaFuncSetAttribute(attn_kernel,
                         cudaFuncAttributeMaxDynamicSharedMemorySize, attn_smem);

    dim3 pgrid(LSEQ / 128, NSLICE);
    proj_fused_kernel<<<pgrid, 256>>>(info, Wq, bq, Wk, bk, Wv, bv);

    dim3 agrid(NQT, NSLICE);
    attn_kernel<<<agrid, 256, attn_smem>>>();

    stats_kernel<<<NSLICE, 32>>>();

    int total4 = NSLICE * LSEQ * EDIM / 4;
    norm_kernel<<<total4 / 256, 256>>>(out);
}